// round 6
// baseline (speedup 1.0000x reference)
#include <cuda_runtime.h>

#define NJ   32
#define TPB  128
#define EPB  (TPB / 4)     // 32 elements per block, 4 threads each
#define OUTC 94

// ---- dynamic smem float offsets ----
#define S_OUT   0                       // EPB*OUTC = 3008 floats
#define S_BASE  (EPB * OUTC)            // 3008  (EPB x 7)
#define S_TGT   (S_BASE + EPB * 7)      // 3232  (4 x 7)
#define S_DB    (S_TGT + 28)            // (7)
#define S_REST  (S_DB + 7)              // (32)
#define S_JLO   (S_REST + 32)           // (32)
#define S_JUP   (S_JLO + 32)            // (32)
#define S_JOFF  (S_JUP + 32)            // (32 x 7)
#define S_P     (S_JOFF + 224)          // (32 x 4)
#define S_TOTAL (S_P + 128)             // 3715 floats = 14860 B

struct Q { float x, y, z, w; };
struct V { float x, y, z; };

__device__ __forceinline__ V vcross(V a, V b) {
    return {a.y * b.z - a.z * b.y,
            a.z * b.x - a.x * b.z,
            a.x * b.y - a.y * b.x};
}

__device__ __forceinline__ V qrot(Q q, V t) {
    V v{q.x, q.y, q.z};
    V u = vcross(v, t);
    u.x = fmaf(q.w, t.x, u.x);
    u.y = fmaf(q.w, t.y, u.y);
    u.z = fmaf(q.w, t.z, u.z);
    V c = vcross(v, u);
    return {fmaf(2.0f, c.x, t.x), fmaf(2.0f, c.y, t.y), fmaf(2.0f, c.z, t.z)};
}

__device__ __forceinline__ Q qmul(Q a, Q b) {
    Q r;
    r.w = a.w * b.w - a.x * b.x - a.y * b.y - a.z * b.z;
    r.x = a.w * b.x + b.w * a.x + a.y * b.z - a.z * b.y;
    r.y = a.w * b.y + b.w * a.y + a.z * b.x - a.x * b.z;
    r.z = a.w * b.z + b.w * a.z + a.x * b.y - a.y * b.x;
    return r;
}

// (t1,q1) <- (t1,q1) o (t2,q2)
__device__ __forceinline__ void se3_acc(V& t1, Q& q1, V t2, Q q2) {
    V r = qrot(q1, t2);
    t1.x += r.x; t1.y += r.y; t1.z += r.z;
    q1 = qmul(q1, q2);
}

// atan2(y,x), y >= 0, x >= 0, not both zero
__device__ __forceinline__ float atan2pos(float y, float x) {
    float mn = fminf(y, x), mx = fmaxf(y, x);
    float r  = __fdividef(mn, mx);
    float r2 = r * r;
    float p = fmaf(r2, -0.0117212f,  0.05265332f);
    p = fmaf(r2, p, -0.11643287f);
    p = fmaf(r2, p,  0.19354346f);
    p = fmaf(r2, p, -0.33262347f);
    p = fmaf(r2, p,  0.99997726f);
    float th = r * p;
    return (y > x) ? (1.57079632679489662f - th) : th;
}

// se3_log for unit quaternion (trig-free tail)
__device__ __forceinline__ void se3_log(V t, Q q, V& rho, V& phi) {
    float sgn = (q.w < 0.0f) ? -1.0f : 1.0f;
    float qx = q.x * sgn, qy = q.y * sgn, qz = q.z * sgn, qw = q.w * sgn;
    float nv2 = qx * qx + qy * qy + qz * qz;
    float nv  = sqrtf(fmaxf(nv2, 1e-14f));
    float angle = 2.0f * atan2pos(nv, qw);
    float wsafe = (fabsf(qw) > 1e-8f) ? qw : 1.0f;
    float scale = (nv < 1e-6f) ? __fdividef(2.0f, wsafe) : __fdividef(angle, nv);
    phi = {qx * scale, qy * scale, qz * scale};

    float th2 = angle * angle;
    float abig = __fdividef(1.0f - 0.5f * scale * qw, th2);
    float a = (angle < 1e-4f) ? (1.0f / 12.0f + th2 * (1.0f / 720.0f)) : abig;

    V pt  = vcross(phi, t);
    V ppt = vcross(phi, pt);
    rho = {t.x - 0.5f * pt.x + a * ppt.x,
           t.y - 0.5f * pt.y + a * ppt.y,
           t.z - 0.5f * pt.z + a * ppt.z};
}

__device__ __forceinline__ void pose_err_log(const float* tp, V at, Q aq,
                                             V& rho, V& phi) {
    Q qi{-tp[3], -tp[4], -tp[5], tp[6]};
    V d{at.x - tp[0], at.y - tp[1], at.z - tp[2]};
    V pe = qrot(qi, d);
    Q qe = qmul(qi, aq);
    se3_log(pe, qe, rho, phi);
}

__global__ void __launch_bounds__(TPB, 6)
ik_residual_kernel(const float* __restrict__ cfg,
                   const float* __restrict__ base,
                   const float* __restrict__ tgt,
                   const float* __restrict__ dbase,
                   const float* __restrict__ rest,
                   const float* __restrict__ joff,
                   const float* __restrict__ jaxis,
                   const float* __restrict__ jlo,
                   const float* __restrict__ jup,
                   float* __restrict__ out) {
    extern __shared__ float s[];

    const int t    = threadIdx.x;
    const int elem = t >> 2;        // 0..31
    const int seg  = t & 3;         // 0..3
    const int e0   = blockIdx.x * EPB;

    // ---- stage constants + base poses ----
    {
        const float* gb = base + (size_t)e0 * 7;
        for (int i = t; i < EPB * 7; i += TPB) s[S_BASE + i] = gb[i];
        for (int i = t; i < 224; i += TPB) s[S_JOFF + i] = __ldg(joff + i);
        if (t < 28) s[S_TGT + t] = __ldg(tgt + t);
        if (t < 7)  s[S_DB + t]  = __ldg(dbase + t);
        if (t < 32) {
            s[S_REST + t] = __ldg(rest + t);
            s[S_JLO + t]  = __ldg(jlo + t);
            s[S_JUP + t]  = __ldg(jup + t);
            float ox = __ldg(joff + t * 7 + 3), oy = __ldg(joff + t * 7 + 4);
            float oz = __ldg(joff + t * 7 + 5), ow = __ldg(joff + t * 7 + 6);
            float ax = __ldg(jaxis + t * 3 + 0), ay = __ldg(jaxis + t * 3 + 1);
            float az = __ldg(jaxis + t * 3 + 2);
            s[S_P + t * 4 + 0] = ow * ax + oy * az - oz * ay;
            s[S_P + t * 4 + 1] = ow * ay + oz * ax - ox * az;
            s[S_P + t * 4 + 2] = ow * az + ox * ay - oy * ax;
            s[S_P + t * 4 + 3] = -(ox * ax + oy * ay + oz * az);
        }
    }
    __syncthreads();

    float* row = s + S_OUT + elem * OUTC;
    const int j0 = seg * 8;

    // ---- load this segment's 8 joint angles (coalesced: lane-stride 32B) ----
    float th[8];
    {
        const float4* c4 = (const float4*)(cfg + (size_t)(e0 + elem) * NJ) + seg * 2;
        float4 ca = __ldg(c4);
        float4 cb = __ldg(c4 + 1);
        th[0] = ca.x; th[1] = ca.y; th[2] = ca.z; th[3] = ca.w;
        th[4] = cb.x; th[5] = cb.y; th[6] = cb.z; th[7] = cb.w;
    }

    // ---- limit / rest residuals for this segment ----
    #pragma unroll
    for (int i = 0; i < 8; i++) {
        const int j = j0 + i;
        float lim = fmaxf(th[i] - s[S_JUP + j], 0.0f)
                  + fminf(th[i] - s[S_JLO + j], 0.0f);
        row[24 + j] = lim * 10.0f;
        row[56 + j] = (th[i] - s[S_REST + j]) * 0.1f;
    }

    // ---- segment product: pairwise tree over 8 leaves ----
    V St; Q Sq;
    {
        auto leaf = [&](int i, V& lt, Q& lq) {
            const int j = j0 + i;
            float sh, ch;
            __sincosf(0.5f * th[i], &sh, &ch);
            const float* o = s + S_JOFF + j * 7;
            const float* p = s + S_P + j * 4;
            lq.x = fmaf(sh, p[0], ch * o[3]);
            lq.y = fmaf(sh, p[1], ch * o[4]);
            lq.z = fmaf(sh, p[2], ch * o[5]);
            lq.w = fmaf(sh, p[3], ch * o[6]);
            lt.x = o[0]; lt.y = o[1]; lt.z = o[2];
        };
        V ta, tb; Q qa, qb;
        leaf(0, St, Sq); leaf(1, ta, qa); se3_acc(St, Sq, ta, qa);
        leaf(2, ta, qa); leaf(3, tb, qb); se3_acc(ta, qa, tb, qb);
        se3_acc(St, Sq, ta, qa);                     // joints 0-3
        V tc; Q qc;
        leaf(4, tc, qc); leaf(5, ta, qa); se3_acc(tc, qc, ta, qa);
        leaf(6, ta, qa); leaf(7, tb, qb); se3_acc(ta, qa, tb, qb);
        se3_acc(tc, qc, ta, qa);                     // joints 4-7
        se3_acc(St, Sq, tc, qc);                     // full segment
    }

    // ---- 4-lane inclusive SE(3) scan (Hillis-Steele, width=4) ----
    #pragma unroll
    for (int d = 1; d <= 2; d <<= 1) {
        V rt; Q rq;
        rt.x = __shfl_up_sync(0xffffffffu, St.x, d, 4);
        rt.y = __shfl_up_sync(0xffffffffu, St.y, d, 4);
        rt.z = __shfl_up_sync(0xffffffffu, St.z, d, 4);
        rq.x = __shfl_up_sync(0xffffffffu, Sq.x, d, 4);
        rq.y = __shfl_up_sync(0xffffffffu, Sq.y, d, 4);
        rq.z = __shfl_up_sync(0xffffffffu, Sq.z, d, 4);
        rq.w = __shfl_up_sync(0xffffffffu, Sq.w, d, 4);
        V ct = rt; Q cq = rq;
        se3_acc(ct, cq, St, Sq);     // (prev) o (mine)
        if (seg >= d) { St = ct; Sq = cq; }
    }

    // ---- T = base o prefix ----
    {
        const float* bp = s + S_BASE + elem * 7;
        V Tt{bp[0], bp[1], bp[2]};
        Q Tq{bp[3], bp[4], bp[5], bp[6]};
        se3_acc(Tt, Tq, St, Sq);

        V rho, phi;
        pose_err_log(s + S_TGT + seg * 7, Tt, Tq, rho, phi);
        row[seg * 6 + 0] = rho.x;
        row[seg * 6 + 1] = rho.y;
        row[seg * 6 + 2] = rho.z;
        row[seg * 6 + 3] = 0.5f * phi.x;
        row[seg * 6 + 4] = 0.5f * phi.y;
        row[seg * 6 + 5] = 0.5f * phi.z;
    }

    // ---- base residuals: warp 0 handles one element per lane ----
    if (t < EPB) {
        const float* bp = s + S_BASE + t * 7;
        V rho, phi;
        pose_err_log(s + S_DB, V{bp[0], bp[1], bp[2]},
                     Q{bp[3], bp[4], bp[5], bp[6]}, rho, phi);
        float* r2 = s + S_OUT + t * OUTC;
        r2[88] = rho.x * 5.0f;
        r2[89] = rho.y * 5.0f;
        r2[90] = rho.z * 5.0f;
        r2[91] = phi.x * 5.0f;
        r2[92] = phi.y * 5.0f;
        r2[93] = phi.z * 5.0f;
    }

    __syncthreads();

    // ---- coalesced flush: EPB*OUTC floats = 752 float4 ----
    {
        float4* go4 = (float4*)(out + (size_t)e0 * OUTC);
        const float4* s4 = (const float4*)(s + S_OUT);
        for (int f = t; f < EPB * OUTC / 4; f += TPB) go4[f] = s4[f];
    }
}

extern "C" void kernel_launch(void* const* d_in, const int* in_sizes, int n_in,
                              void* d_out, int out_size) {
    const float* cfg   = (const float*)d_in[0];
    const float* base  = (const float*)d_in[1];
    const float* tgt   = (const float*)d_in[2];
    const float* dbase = (const float*)d_in[3];
    const float* rest  = (const float*)d_in[4];
    const float* joff  = (const float*)d_in[5];
    const float* jaxis = (const float*)d_in[6];
    const float* jlo   = (const float*)d_in[7];
    const float* jup   = (const float*)d_in[8];
    float* out = (float*)d_out;

    const int smem_bytes = S_TOTAL * sizeof(float);   // 14860
    cudaFuncSetAttribute(ik_residual_kernel,
                         cudaFuncAttributeMaxDynamicSharedMemorySize, smem_bytes);

    int B = in_sizes[0] / NJ;     // 65536
    int nblocks = B / EPB;        // 2048

    ik_residual_kernel<<<nblocks, TPB, smem_bytes>>>(cfg, base, tgt, dbase, rest,
                                                     joff, jaxis, jlo, jup, out);
}

// round 7
// speedup vs baseline: 1.2033x; 1.2033x over previous
#include <cuda_runtime.h>

#define NJ   32
#define TPB  64
#define OUTC 94

// ---- dynamic smem float offsets ----
#define S_OUT   0                       // TPB*OUTC = 6016 floats (also cfg-stage scratch)
#define S_BASE  (TPB * OUTC)            // 6016  (TPB x 7)
#define S_TGT   (S_BASE + TPB * 7)      // 6464  (4 x 7)
#define S_DB    (S_TGT + 28)            // (7)
#define S_REST  (S_DB + 7)              // (32)
#define S_JLO   (S_REST + 32)           // (32)
#define S_JUP   (S_JLO + 32)            // (32)
#define S_JOFF  (S_JUP + 32)            // (32 x 7)
#define S_P     (S_JOFF + 224)          // (32 x 4)
#define S_TOTAL (S_P + 128)             // 6947 floats = 27788 B

#define CFG_PAD 36                      // padded cfg row stride (16B-aligned, phase-conflict-free)

struct Q { float x, y, z, w; };
struct V { float x, y, z; };

__device__ __forceinline__ V vcross(V a, V b) {
    return {a.y * b.z - a.z * b.y,
            a.z * b.x - a.x * b.z,
            a.x * b.y - a.y * b.x};
}

__device__ __forceinline__ V qrot(Q q, V t) {
    V v{q.x, q.y, q.z};
    V u = vcross(v, t);
    u.x = fmaf(q.w, t.x, u.x);
    u.y = fmaf(q.w, t.y, u.y);
    u.z = fmaf(q.w, t.z, u.z);
    V c = vcross(v, u);
    return {fmaf(2.0f, c.x, t.x), fmaf(2.0f, c.y, t.y), fmaf(2.0f, c.z, t.z)};
}

__device__ __forceinline__ Q qmul(Q a, Q b) {
    Q r;
    r.w = a.w * b.w - a.x * b.x - a.y * b.y - a.z * b.z;
    r.x = a.w * b.x + b.w * a.x + a.y * b.z - a.z * b.y;
    r.y = a.w * b.y + b.w * a.y + a.z * b.x - a.x * b.z;
    r.z = a.w * b.z + b.w * a.z + a.x * b.y - a.y * b.x;
    return r;
}

// (t1,q1) <- (t1,q1) o (t2,q2)
__device__ __forceinline__ void se3_acc(V& t1, Q& q1, V t2, Q q2) {
    V r = qrot(q1, t2);
    t1.x += r.x; t1.y += r.y; t1.z += r.z;
    q1 = qmul(q1, q2);
}

// atan2(y,x), y >= 0, x >= 0, not both zero
__device__ __forceinline__ float atan2pos(float y, float x) {
    float mn = fminf(y, x), mx = fmaxf(y, x);
    float r  = __fdividef(mn, mx);
    float r2 = r * r;
    float p = fmaf(r2, -0.0117212f,  0.05265332f);
    p = fmaf(r2, p, -0.11643287f);
    p = fmaf(r2, p,  0.19354346f);
    p = fmaf(r2, p, -0.33262347f);
    p = fmaf(r2, p,  0.99997726f);
    float th = r * p;
    return (y > x) ? (1.57079632679489662f - th) : th;
}

// se3_log for unit quaternion (trig-free tail)
__device__ __forceinline__ void se3_log(V t, Q q, V& rho, V& phi) {
    float sgn = (q.w < 0.0f) ? -1.0f : 1.0f;
    float qx = q.x * sgn, qy = q.y * sgn, qz = q.z * sgn, qw = q.w * sgn;
    float nv2 = qx * qx + qy * qy + qz * qz;
    float nv  = sqrtf(fmaxf(nv2, 1e-14f));
    float angle = 2.0f * atan2pos(nv, qw);
    float wsafe = (fabsf(qw) > 1e-8f) ? qw : 1.0f;
    float scale = (nv < 1e-6f) ? __fdividef(2.0f, wsafe) : __fdividef(angle, nv);
    phi = {qx * scale, qy * scale, qz * scale};

    float th2 = angle * angle;
    float abig = __fdividef(1.0f - 0.5f * scale * qw, th2);
    float a = (angle < 1e-4f) ? (1.0f / 12.0f + th2 * (1.0f / 720.0f)) : abig;

    V pt  = vcross(phi, t);
    V ppt = vcross(phi, pt);
    rho = {t.x - 0.5f * pt.x + a * ppt.x,
           t.y - 0.5f * pt.y + a * ppt.y,
           t.z - 0.5f * pt.z + a * ppt.z};
}

__device__ __forceinline__ void pose_err_log(const float* tp, V at, Q aq,
                                             V& rho, V& phi) {
    Q qi{-tp[3], -tp[4], -tp[5], tp[6]};
    V d{at.x - tp[0], at.y - tp[1], at.z - tp[2]};
    V pe = qrot(qi, d);
    Q qe = qmul(qi, aq);
    se3_log(pe, qe, rho, phi);
}

__global__ void __launch_bounds__(TPB, 8)
ik_residual_kernel(const float* __restrict__ cfg,
                   const float* __restrict__ base,
                   const float* __restrict__ tgt,
                   const float* __restrict__ dbase,
                   const float* __restrict__ rest,
                   const float* __restrict__ joff,
                   const float* __restrict__ jaxis,
                   const float* __restrict__ jlo,
                   const float* __restrict__ jup,
                   float* __restrict__ out) {
    extern __shared__ float s[];

    const int t  = threadIdx.x;
    const int b0 = blockIdx.x * TPB;

    // ---- stage constants + base poses + cfg tile (cfg -> S_OUT scratch, padded rows) ----
    {
        const float* gb = base + (size_t)b0 * 7;
        #pragma unroll
        for (int i = t; i < TPB * 7; i += TPB) s[S_BASE + i] = gb[i];

        // coalesced cfg tile: TPB rows x 32 floats -> padded rows of CFG_PAD
        const float4* gc = (const float4*)(cfg + (size_t)b0 * NJ);
        #pragma unroll
        for (int f = t; f < TPB * (NJ / 4); f += TPB) {
            int r = f >> 3;            // row (8 float4 per row)
            int c = f & 7;
            float4 v = __ldg(gc + f);
            *(float4*)(s + S_OUT + r * CFG_PAD + c * 4) = v;
        }

        #pragma unroll
        for (int i = t; i < 224; i += TPB) s[S_JOFF + i] = __ldg(joff + i);
        if (t < 28) s[S_TGT + t] = __ldg(tgt + t);
        if (t < 7)  s[S_DB + t]  = __ldg(dbase + t);
        if (t < 32) {
            s[S_REST + t] = __ldg(rest + t);
            s[S_JLO + t]  = __ldg(jlo + t);
            s[S_JUP + t]  = __ldg(jup + t);
            float ox = __ldg(joff + t * 7 + 3), oy = __ldg(joff + t * 7 + 4);
            float oz = __ldg(joff + t * 7 + 5), ow = __ldg(joff + t * 7 + 6);
            float ax = __ldg(jaxis + t * 3 + 0), ay = __ldg(jaxis + t * 3 + 1);
            float az = __ldg(jaxis + t * 3 + 2);
            s[S_P + t * 4 + 0] = ow * ax + oy * az - oz * ay;
            s[S_P + t * 4 + 1] = ow * ay + oz * ax - ox * az;
            s[S_P + t * 4 + 2] = ow * az + ox * ay - oy * ax;
            s[S_P + t * 4 + 3] = -(ox * ax + oy * ay + oz * az);
        }
    }
    __syncthreads();

    // read own base pose + cfg row from smem (conflict-free strides)
    float bp[7];
    #pragma unroll
    for (int i = 0; i < 7; i++) bp[i] = s[S_BASE + t * 7 + i];

    float th[NJ];
    {
        const float4* cr = (const float4*)(s + S_OUT + t * CFG_PAD);
        #pragma unroll
        for (int i = 0; i < NJ / 4; i++) {
            float4 v = cr[i];
            th[4*i+0] = v.x; th[4*i+1] = v.y; th[4*i+2] = v.z; th[4*i+3] = v.w;
        }
    }
    __syncthreads();   // cfg scratch becomes output staging

    float* row = s + S_OUT + t * OUTC;

    V Tt{bp[0], bp[1], bp[2]};
    Q Tq{bp[3], bp[4], bp[5], bp[6]};

    // ---- tree-structured FK: 4 segments of 8 joints ----
    #pragma unroll
    for (int seg = 0; seg < 4; seg++) {
        const int j0 = seg * 8;

        // leaf joint quats M_j = ch*oq_j + sh*P_j + limit/rest residuals
        Q M[8];
        #pragma unroll
        for (int i = 0; i < 8; i++) {
            const int j = j0 + i;
            float thj = th[j];
            float lim = fmaxf(thj - s[S_JUP + j], 0.0f)
                      + fminf(thj - s[S_JLO + j], 0.0f);
            row[24 + j] = lim * 10.0f;
            row[56 + j] = (thj - s[S_REST + j]) * 0.1f;

            float sh, ch;
            __sincosf(0.5f * thj, &sh, &ch);
            const float* o = s + S_JOFF + j * 7;
            const float* p = s + S_P + j * 4;
            M[i].x = fmaf(sh, p[0], ch * o[3]);
            M[i].y = fmaf(sh, p[1], ch * o[4]);
            M[i].z = fmaf(sh, p[2], ch * o[5]);
            M[i].w = fmaf(sh, p[3], ch * o[6]);
        }

        const float* o0 = s + S_JOFF + (j0 + 0) * 7;
        const float* o1 = s + S_JOFF + (j0 + 1) * 7;
        const float* o2 = s + S_JOFF + (j0 + 2) * 7;
        const float* o3 = s + S_JOFF + (j0 + 3) * 7;
        const float* o4 = s + S_JOFF + (j0 + 4) * 7;
        const float* o5 = s + S_JOFF + (j0 + 5) * 7;
        const float* o6 = s + S_JOFF + (j0 + 6) * 7;
        const float* o7 = s + S_JOFF + (j0 + 7) * 7;

        // level 1: 4 independent composes
        V t01{o0[0], o0[1], o0[2]}; Q q01 = M[0];
        se3_acc(t01, q01, V{o1[0], o1[1], o1[2]}, M[1]);
        V t23{o2[0], o2[1], o2[2]}; Q q23 = M[2];
        se3_acc(t23, q23, V{o3[0], o3[1], o3[2]}, M[3]);
        V t45{o4[0], o4[1], o4[2]}; Q q45 = M[4];
        se3_acc(t45, q45, V{o5[0], o5[1], o5[2]}, M[5]);
        V t67{o6[0], o6[1], o6[2]}; Q q67 = M[6];
        se3_acc(t67, q67, V{o7[0], o7[1], o7[2]}, M[7]);

        // level 2 + 3
        se3_acc(t01, q01, t23, q23);
        se3_acc(t45, q45, t67, q67);
        se3_acc(t01, q01, t45, q45);

        // chain into running pose (prefix at target link)
        se3_acc(Tt, Tq, t01, q01);

        V rho, phi;
        pose_err_log(s + S_TGT + seg * 7, Tt, Tq, rho, phi);
        row[seg * 6 + 0] = rho.x;
        row[seg * 6 + 1] = rho.y;
        row[seg * 6 + 2] = rho.z;
        row[seg * 6 + 3] = 0.5f * phi.x;
        row[seg * 6 + 4] = 0.5f * phi.y;
        row[seg * 6 + 5] = 0.5f * phi.z;
    }

    // ---- base residual ----
    {
        V rho, phi;
        pose_err_log(s + S_DB, V{bp[0], bp[1], bp[2]},
                     Q{bp[3], bp[4], bp[5], bp[6]}, rho, phi);
        row[88] = rho.x * 5.0f;
        row[89] = rho.y * 5.0f;
        row[90] = rho.z * 5.0f;
        row[91] = phi.x * 5.0f;
        row[92] = phi.y * 5.0f;
        row[93] = phi.z * 5.0f;
    }

    __syncthreads();

    // ---- flat vectorized flush: TPB*OUTC floats = 1504 float4 ----
    {
        float4* go4 = (float4*)(out + (size_t)b0 * OUTC);
        const float4* s4 = (const float4*)(s + S_OUT);
        for (int f = t; f < TPB * OUTC / 4; f += TPB) go4[f] = s4[f];
    }
}

extern "C" void kernel_launch(void* const* d_in, const int* in_sizes, int n_in,
                              void* d_out, int out_size) {
    const float* cfg   = (const float*)d_in[0];
    const float* base  = (const float*)d_in[1];
    const float* tgt   = (const float*)d_in[2];
    const float* dbase = (const float*)d_in[3];
    const float* rest  = (const float*)d_in[4];
    const float* joff  = (const float*)d_in[5];
    const float* jaxis = (const float*)d_in[6];
    const float* jlo   = (const float*)d_in[7];
    const float* jup   = (const float*)d_in[8];
    float* out = (float*)d_out;

    const int smem_bytes = S_TOTAL * sizeof(float);   // 27788
    cudaFuncSetAttribute(ik_residual_kernel,
                         cudaFuncAttributeMaxDynamicSharedMemorySize, smem_bytes);

    int B = in_sizes[0] / NJ;     // 65536
    int nblocks = B / TPB;        // 1024

    ik_residual_kernel<<<nblocks, TPB, smem_bytes>>>(cfg, base, tgt, dbase, rest,
                                                     joff, jaxis, jlo, jup, out);
}